// round 3
// baseline (speedup 1.0000x reference)
#include <cuda_runtime.h>
#include <math.h>

#define D 256
#define HID 512
#define NPB 16          // nodes per block
#define THREADS 256

// Scratch: node embeddings for all 65536 nodes
__device__ float g_nodes[65536 * D];

typedef unsigned long long u64;

__device__ __forceinline__ u64 pack2(float v) {
    u64 r;
    asm("mov.b64 %0, {%1, %1};" : "=l"(r) : "f"(v));
    return r;
}
__device__ __forceinline__ void fma2(u64& a, u64 x, u64 w) {
    asm("fma.rn.f32x2 %0, %1, %2, %0;" : "+l"(a) : "l"(x), "l"(w));
}
__device__ __forceinline__ float2 unpack2(u64 v) {
    float2 f;
    asm("mov.b64 {%0, %1}, %2;" : "=f"(f.x), "=f"(f.y) : "l"(v));
    return f;
}

// ---------------------------------------------------------------------------
// Embedding gather: g_nodes[n] = comp_table[component_ids[n]]
// ---------------------------------------------------------------------------
__global__ void embed_kernel(const int* __restrict__ comp_ids,
                             const float* __restrict__ comp_table,
                             int n_nodes) {
    int idx = blockIdx.x * blockDim.x + threadIdx.x;   // one float4 per thread
    int total = n_nodes * (D / 4);
    if (idx >= total) return;
    int n = idx >> 6;          // / 64
    int c = idx & 63;
    const float4* src = (const float4*)(comp_table + (long)comp_ids[n] * D);
    ((float4*)(g_nodes + (long)n * D))[c] = src[c];
}

// ---------------------------------------------------------------------------
// One level: per block, NPB nodes, all same branch (binary/ternary).
// Phase-grouped position mapping: g = (blockIdx.x + blk_off)*NPB + k
//   pos_in_level = (g % 4096) * PHASES + (g / 4096)
// so all nodes of a block share the same within-tree slot -> uniform branch.
// ---------------------------------------------------------------------------
template <bool TERN>
__global__ void __launch_bounds__(THREADS, 2)
level_kernel(const int* __restrict__ lvl_idx, int phases, int blk_off,
             const int* __restrict__ op_ids,
             const int* __restrict__ lc_arr, const int* __restrict__ rc_arr,
             const int* __restrict__ tc_arr,
             const float* __restrict__ op_table,
             const float* __restrict__ W1, const float* __restrict__ b1,
             const float* __restrict__ W2, const float* __restrict__ b2,
             const float* __restrict__ gamma, const float* __restrict__ beta,
             float* __restrict__ dense_out)  // non-null: write out[pos]; else scatter g_nodes[node]
{
    constexpr int IN_DIM = TERN ? 1024 : 768;
    extern __shared__ float smem[];
    float* sx = smem;                        // [NPB][IN_DIM]
    float* sh = smem + NPB * IN_DIM;         // [NPB][HID]
    float* sy = sh + NPB * HID;              // [NPB][D]

    __shared__ int s_node[NPB], s_pos[NPB], s_lc[NPB], s_rc[NPB], s_tc[NPB], s_op[NPB];

    const int tid = threadIdx.x;
    if (tid < NPB) {
        int g = (blockIdx.x + blk_off) * NPB + tid;
        int pos = (g & 4095) * phases + (g >> 12);
        int node = lvl_idx[pos];
        s_pos[tid]  = pos;
        s_node[tid] = node;
        s_lc[tid]   = lc_arr[node];
        s_rc[tid]   = rc_arr[node];
        s_tc[tid]   = tc_arr[node];
        s_op[tid]   = op_ids[node];
    }
    __syncthreads();

    // ---- gather X = [op | left | right | (third)] -------------------------
    #pragma unroll 4
    for (int n = 0; n < NPB; n++) {
        sx[n * IN_DIM + tid]       = op_table[s_op[n] * D + tid];
        sx[n * IN_DIM + 256 + tid] = g_nodes[(long)s_lc[n] * D + tid];
        sx[n * IN_DIM + 512 + tid] = g_nodes[(long)s_rc[n] * D + tid];
        if (TERN)
            sx[n * IN_DIM + 768 + tid] = g_nodes[(long)s_tc[n] * D + tid];
    }
    __syncthreads();

    // ---- phase 1: H = gelu(X @ W1 + b1) ----------------------------------
    // 256 threads = 64 col-groups (8 cols, 4 packed pairs) x 4 node-groups (4 nodes)
    {
        const int jg = tid & 63;
        const int ng = tid >> 6;
        const int j0 = jg * 8;
        u64 acc[4][4];
        {
            ulonglong2 bv0 = *(const ulonglong2*)(b1 + j0);
            ulonglong2 bv1 = *(const ulonglong2*)(b1 + j0 + 4);
            #pragma unroll
            for (int u = 0; u < 4; u++) {
                acc[u][0] = bv0.x; acc[u][1] = bv0.y;
                acc[u][2] = bv1.x; acc[u][3] = bv1.y;
            }
        }
        const float* xb = sx + ng * 4 * IN_DIM;
        #pragma unroll 4
        for (int i = 0; i < IN_DIM; i++) {
            ulonglong2 w0 = *(const ulonglong2*)(W1 + i * HID + j0);
            ulonglong2 w1 = *(const ulonglong2*)(W1 + i * HID + j0 + 4);
            #pragma unroll
            for (int u = 0; u < 4; u++) {
                u64 xx = pack2(xb[u * IN_DIM + i]);
                fma2(acc[u][0], xx, w0.x);
                fma2(acc[u][1], xx, w0.y);
                fma2(acc[u][2], xx, w1.x);
                fma2(acc[u][3], xx, w1.y);
            }
        }
        #pragma unroll
        for (int u = 0; u < 4; u++) {
            #pragma unroll
            for (int p = 0; p < 4; p++) {
                float2 a = unpack2(acc[u][p]);
                float g0 = 0.5f * a.x * (1.0f + erff(a.x * 0.70710678118654752f));
                float g1 = 0.5f * a.y * (1.0f + erff(a.y * 0.70710678118654752f));
                int base = (ng * 4 + u) * HID + j0 + p * 2;
                sh[base]     = g0;
                sh[base + 1] = g1;
            }
        }
    }
    __syncthreads();

    // ---- phase 2: Y = H @ W2 + b2 + residual -----------------------------
    // 256 threads = 32 col-groups (8 cols, 4 packed pairs) x 8 node-groups (2 nodes)
    {
        const int dg = tid & 31;
        const int ng = tid >> 5;
        const int d0 = dg * 8;
        u64 acc[2][4];
        {
            ulonglong2 bv0 = *(const ulonglong2*)(b2 + d0);
            ulonglong2 bv1 = *(const ulonglong2*)(b2 + d0 + 4);
            #pragma unroll
            for (int u = 0; u < 2; u++) {
                acc[u][0] = bv0.x; acc[u][1] = bv0.y;
                acc[u][2] = bv1.x; acc[u][3] = bv1.y;
            }
        }
        const float* hb = sh + ng * 2 * HID;
        #pragma unroll 4
        for (int j = 0; j < HID; j++) {
            ulonglong2 w0 = *(const ulonglong2*)(W2 + j * D + d0);
            ulonglong2 w1 = *(const ulonglong2*)(W2 + j * D + d0 + 4);
            #pragma unroll
            for (int u = 0; u < 2; u++) {
                u64 hh = pack2(hb[u * HID + j]);
                fma2(acc[u][0], hh, w0.x);
                fma2(acc[u][1], hh, w0.y);
                fma2(acc[u][2], hh, w1.x);
                fma2(acc[u][3], hh, w1.y);
            }
        }
        #pragma unroll
        for (int u = 0; u < 2; u++) {
            int n = ng * 2 + u;
            #pragma unroll
            for (int p = 0; p < 4; p++) {
                float2 a = unpack2(acc[u][p]);
                #pragma unroll
                for (int q = 0; q < 2; q++) {
                    int d = d0 + p * 2 + q;
                    float av = q ? a.y : a.x;
                    float le = sx[n * IN_DIM + 256 + d];
                    float re = sx[n * IN_DIM + 512 + d];
                    float y;
                    if (TERN) {
                        float te = sx[n * IN_DIM + 768 + d];
                        y = av + (le + re + te) * (1.0f / 3.0f);
                    } else {
                        y = av + le + re;
                    }
                    sy[n * D + d] = y;
                }
            }
        }
    }
    __syncthreads();

    // ---- phase 3: LayerNorm + writeback ----------------------------------
    {
        const int warp = tid >> 5;
        const int lane = tid & 31;
        #pragma unroll
        for (int nn = 0; nn < 2; nn++) {
            int n = warp * 2 + nn;
            float vals[8];
            float s = 0.0f, s2 = 0.0f;
            #pragma unroll
            for (int k = 0; k < 8; k++) {
                float v = sy[n * D + lane + k * 32];
                vals[k] = v;
                s += v;
                s2 = fmaf(v, v, s2);
            }
            #pragma unroll
            for (int off = 16; off > 0; off >>= 1) {
                s  += __shfl_xor_sync(0xFFFFFFFF, s, off);
                s2 += __shfl_xor_sync(0xFFFFFFFF, s2, off);
            }
            float mu  = s * (1.0f / 256.0f);
            float var = s2 * (1.0f / 256.0f) - mu * mu;
            float inv = rsqrtf(var + 1e-5f);
            float* dst = dense_out ? (dense_out + (long)s_pos[n] * D)
                                   : (g_nodes + (long)s_node[n] * D);
            #pragma unroll
            for (int k = 0; k < 8; k++) {
                int d = lane + k * 32;
                dst[d] = (vals[k] - mu) * inv * gamma[d] + beta[d];
            }
        }
    }
}

// ---------------------------------------------------------------------------
extern "C" void kernel_launch(void* const* d_in, const int* in_sizes, int n_in,
                              void* d_out, int out_size) {
    const int*   comp_ids   = (const int*)d_in[0];
    const int*   op_ids     = (const int*)d_in[1];
    const int*   lc         = (const int*)d_in[2];
    const int*   rc         = (const int*)d_in[3];
    const int*   tc         = (const int*)d_in[4];
    const int*   lvl2       = (const int*)d_in[5];
    const int*   lvl1       = (const int*)d_in[6];
    const int*   lvl0       = (const int*)d_in[7];
    const float* comp_table = (const float*)d_in[8];
    const float* op_table   = (const float*)d_in[9];
    const float* W1b        = (const float*)d_in[10];
    const float* b1b        = (const float*)d_in[11];
    const float* W2b        = (const float*)d_in[12];
    const float* b2b        = (const float*)d_in[13];
    const float* W1t        = (const float*)d_in[14];
    const float* b1t        = (const float*)d_in[15];
    const float* W2t        = (const float*)d_in[16];
    const float* b2t        = (const float*)d_in[17];
    const float* gamma      = (const float*)d_in[18];
    const float* beta       = (const float*)d_in[19];
    float* out = (float*)d_out;

    const int n_nodes = in_sizes[0];                 // 65536
    const int L2 = in_sizes[5];                      // 16384
    const int L1 = in_sizes[6];                      // 8192
    const int L0 = in_sizes[7];                      // 4096

    const int SMEM_BIN  = (NPB * 768  + NPB * HID + NPB * D) * 4;  // 98304
    const int SMEM_TERN = (NPB * 1024 + NPB * HID + NPB * D) * 4;  // 114688

    cudaFuncSetAttribute(level_kernel<false>,
                         cudaFuncAttributeMaxDynamicSharedMemorySize, SMEM_BIN);
    cudaFuncSetAttribute(level_kernel<true>,
                         cudaFuncAttributeMaxDynamicSharedMemorySize, SMEM_TERN);

    // 1) embeddings for all nodes
    {
        int total = n_nodes * (D / 4);
        embed_kernel<<<(total + 255) / 256, 256>>>(comp_ids, comp_table, n_nodes);
    }

    // 2) lvl2, ternary slot (phase 0): first 4096 logical nodes -> 256 blocks
    level_kernel<true><<<L0 / NPB, THREADS, SMEM_TERN>>>(
        lvl2, /*phases=*/4, /*blk_off=*/0,
        op_ids, lc, rc, tc, op_table,
        W1t, b1t, W2t, b2t, gamma, beta, nullptr);

    // 3) lvl2, binary slots (phases 1..3): 12288 nodes -> 768 blocks, offset 256
    level_kernel<false><<<(L2 - L0) / NPB, THREADS, SMEM_BIN>>>(
        lvl2, /*phases=*/4, /*blk_off=*/L0 / NPB,
        op_ids, lc, rc, tc, op_table,
        W1b, b1b, W2b, b2b, gamma, beta, nullptr);

    // 4) lvl1 (all binary): 8192 nodes -> 512 blocks
    level_kernel<false><<<L1 / NPB, THREADS, SMEM_BIN>>>(
        lvl1, /*phases=*/2, /*blk_off=*/0,
        op_ids, lc, rc, tc, op_table,
        W1b, b1b, W2b, b2b, gamma, beta, nullptr);

    // 5) lvl0 (all binary): 4096 nodes -> 256 blocks, writes d_out densely
    level_kernel<false><<<L0 / NPB, THREADS, SMEM_BIN>>>(
        lvl0, /*phases=*/1, /*blk_off=*/0,
        op_ids, lc, rc, tc, op_table,
        W1b, b1b, W2b, b2b, gamma, beta, out);

    (void)n_in; (void)out_size;
}

// round 4
// speedup vs baseline: 1.6190x; 1.6190x over previous
#include <cuda_runtime.h>
#include <math.h>

#define D 256
#define HID 512
#define NPB 16          // nodes per block
#define THREADS 256

// Scratch: node embeddings for all 65536 nodes
__device__ float g_nodes[65536 * D];

typedef unsigned long long u64;

__device__ __forceinline__ u64 pack2(float v) {
    u64 r;
    asm("mov.b64 %0, {%1, %1};" : "=l"(r) : "f"(v));
    return r;
}
__device__ __forceinline__ void fma2(u64& a, u64 x, u64 w) {
    asm("fma.rn.f32x2 %0, %1, %2, %0;" : "+l"(a) : "l"(x), "l"(w));
}
__device__ __forceinline__ float2 unpack2(u64 v) {
    float2 f;
    asm("mov.b64 {%0, %1}, %2;" : "=f"(f.x), "=f"(f.y) : "l"(v));
    return f;
}

// ---------------------------------------------------------------------------
// Embedding gather: g_nodes[n] = comp_table[component_ids[n]]
// ---------------------------------------------------------------------------
__global__ void embed_kernel(const int* __restrict__ comp_ids,
                             const float* __restrict__ comp_table,
                             int n_nodes) {
    int idx = blockIdx.x * blockDim.x + threadIdx.x;   // one float4 per thread
    int total = n_nodes * (D / 4);
    if (idx >= total) return;
    int n = idx >> 6;          // / 64
    int c = idx & 63;
    const float4* src = (const float4*)(comp_table + (long)comp_ids[n] * D);
    ((float4*)(g_nodes + (long)n * D))[c] = src[c];
}

// ---------------------------------------------------------------------------
// One level: per block, NPB nodes, all same branch (binary/ternary).
// Phase-grouped position mapping: g = (blockIdx.x + blk_off)*NPB + k
//   pos_in_level = (g % 4096) * PHASES + (g / 4096)
// so all nodes of a block share the same within-tree slot -> uniform branch.
// ---------------------------------------------------------------------------
template <bool TERN>
__global__ void __launch_bounds__(THREADS, 2)
level_kernel(const int* __restrict__ lvl_idx, int phases, int blk_off,
             const int* __restrict__ op_ids,
             const int* __restrict__ lc_arr, const int* __restrict__ rc_arr,
             const int* __restrict__ tc_arr,
             const float* __restrict__ op_table,
             const float* __restrict__ W1, const float* __restrict__ b1,
             const float* __restrict__ W2, const float* __restrict__ b2,
             const float* __restrict__ gamma, const float* __restrict__ beta,
             float* __restrict__ dense_out)  // non-null: write out[pos]; else scatter g_nodes[node]
{
    constexpr int IN_DIM = TERN ? 1024 : 768;
    extern __shared__ float smem[];
    float* sx = smem;                        // [NPB][IN_DIM]
    float* sh = smem + NPB * IN_DIM;         // [NPB][HID]
    float* sy = sh + NPB * HID;              // [NPB][D]

    __shared__ int s_node[NPB], s_pos[NPB], s_lc[NPB], s_rc[NPB], s_tc[NPB], s_op[NPB];

    const int tid = threadIdx.x;
    if (tid < NPB) {
        int g = (blockIdx.x + blk_off) * NPB + tid;
        int pos = (g & 4095) * phases + (g >> 12);
        int node = lvl_idx[pos];
        s_pos[tid]  = pos;
        s_node[tid] = node;
        s_lc[tid]   = lc_arr[node];
        s_rc[tid]   = rc_arr[node];
        s_tc[tid]   = tc_arr[node];
        s_op[tid]   = op_ids[node];
    }
    __syncthreads();

    // ---- gather X = [op | left | right | (third)] -------------------------
    #pragma unroll 4
    for (int n = 0; n < NPB; n++) {
        sx[n * IN_DIM + tid]       = op_table[s_op[n] * D + tid];
        sx[n * IN_DIM + 256 + tid] = g_nodes[(long)s_lc[n] * D + tid];
        sx[n * IN_DIM + 512 + tid] = g_nodes[(long)s_rc[n] * D + tid];
        if (TERN)
            sx[n * IN_DIM + 768 + tid] = g_nodes[(long)s_tc[n] * D + tid];
    }
    __syncthreads();

    // ---- phase 1: H = gelu(X @ W1 + b1) ----------------------------------
    // 256 threads = 64 col-groups (8 cols, 4 packed pairs) x 4 node-groups (4 nodes)
    {
        const int jg = tid & 63;
        const int ng = tid >> 6;
        const int j0 = jg * 8;
        u64 acc[4][4];
        {
            ulonglong2 bv0 = *(const ulonglong2*)(b1 + j0);
            ulonglong2 bv1 = *(const ulonglong2*)(b1 + j0 + 4);
            #pragma unroll
            for (int u = 0; u < 4; u++) {
                acc[u][0] = bv0.x; acc[u][1] = bv0.y;
                acc[u][2] = bv1.x; acc[u][3] = bv1.y;
            }
        }
        const float* xb = sx + ng * 4 * IN_DIM;
        #pragma unroll 4
        for (int i = 0; i < IN_DIM; i++) {
            ulonglong2 w0 = *(const ulonglong2*)(W1 + i * HID + j0);
            ulonglong2 w1 = *(const ulonglong2*)(W1 + i * HID + j0 + 4);
            #pragma unroll
            for (int u = 0; u < 4; u++) {
                u64 xx = pack2(xb[u * IN_DIM + i]);
                fma2(acc[u][0], xx, w0.x);
                fma2(acc[u][1], xx, w0.y);
                fma2(acc[u][2], xx, w1.x);
                fma2(acc[u][3], xx, w1.y);
            }
        }
        #pragma unroll
        for (int u = 0; u < 4; u++) {
            #pragma unroll
            for (int p = 0; p < 4; p++) {
                float2 a = unpack2(acc[u][p]);
                float g0 = 0.5f * a.x * (1.0f + erff(a.x * 0.70710678118654752f));
                float g1 = 0.5f * a.y * (1.0f + erff(a.y * 0.70710678118654752f));
                int base = (ng * 4 + u) * HID + j0 + p * 2;
                sh[base]     = g0;
                sh[base + 1] = g1;
            }
        }
    }
    __syncthreads();

    // ---- phase 2: Y = H @ W2 + b2 + residual -----------------------------
    // 256 threads = 32 col-groups (8 cols, 4 packed pairs) x 8 node-groups (2 nodes)
    {
        const int dg = tid & 31;
        const int ng = tid >> 5;
        const int d0 = dg * 8;
        u64 acc[2][4];
        {
            ulonglong2 bv0 = *(const ulonglong2*)(b2 + d0);
            ulonglong2 bv1 = *(const ulonglong2*)(b2 + d0 + 4);
            #pragma unroll
            for (int u = 0; u < 2; u++) {
                acc[u][0] = bv0.x; acc[u][1] = bv0.y;
                acc[u][2] = bv1.x; acc[u][3] = bv1.y;
            }
        }
        const float* hb = sh + ng * 2 * HID;
        #pragma unroll 4
        for (int j = 0; j < HID; j++) {
            ulonglong2 w0 = *(const ulonglong2*)(W2 + j * D + d0);
            ulonglong2 w1 = *(const ulonglong2*)(W2 + j * D + d0 + 4);
            #pragma unroll
            for (int u = 0; u < 2; u++) {
                u64 hh = pack2(hb[u * HID + j]);
                fma2(acc[u][0], hh, w0.x);
                fma2(acc[u][1], hh, w0.y);
                fma2(acc[u][2], hh, w1.x);
                fma2(acc[u][3], hh, w1.y);
            }
        }
        #pragma unroll
        for (int u = 0; u < 2; u++) {
            int n = ng * 2 + u;
            #pragma unroll
            for (int p = 0; p < 4; p++) {
                float2 a = unpack2(acc[u][p]);
                #pragma unroll
                for (int q = 0; q < 2; q++) {
                    int d = d0 + p * 2 + q;
                    float av = q ? a.y : a.x;
                    float le = sx[n * IN_DIM + 256 + d];
                    float re = sx[n * IN_DIM + 512 + d];
                    float y;
                    if (TERN) {
                        float te = sx[n * IN_DIM + 768 + d];
                        y = av + (le + re + te) * (1.0f / 3.0f);
                    } else {
                        y = av + le + re;
                    }
                    sy[n * D + d] = y;
                }
            }
        }
    }
    __syncthreads();

    // ---- phase 3: LayerNorm + writeback ----------------------------------
    {
        const int warp = tid >> 5;
        const int lane = tid & 31;
        #pragma unroll
        for (int nn = 0; nn < 2; nn++) {
            int n = warp * 2 + nn;
            float vals[8];
            float s = 0.0f, s2 = 0.0f;
            #pragma unroll
            for (int k = 0; k < 8; k++) {
                float v = sy[n * D + lane + k * 32];
                vals[k] = v;
                s += v;
                s2 = fmaf(v, v, s2);
            }
            #pragma unroll
            for (int off = 16; off > 0; off >>= 1) {
                s  += __shfl_xor_sync(0xFFFFFFFF, s, off);
                s2 += __shfl_xor_sync(0xFFFFFFFF, s2, off);
            }
            float mu  = s * (1.0f / 256.0f);
            float var = s2 * (1.0f / 256.0f) - mu * mu;
            float inv = rsqrtf(var + 1e-5f);
            float* dst = dense_out ? (dense_out + (long)s_pos[n] * D)
                                   : (g_nodes + (long)s_node[n] * D);
            #pragma unroll
            for (int k = 0; k < 8; k++) {
                int d = lane + k * 32;
                dst[d] = (vals[k] - mu) * inv * gamma[d] + beta[d];
            }
        }
    }
}

// ---------------------------------------------------------------------------
extern "C" void kernel_launch(void* const* d_in, const int* in_sizes, int n_in,
                              void* d_out, int out_size) {
    const int*   comp_ids   = (const int*)d_in[0];
    const int*   op_ids     = (const int*)d_in[1];
    const int*   lc         = (const int*)d_in[2];
    const int*   rc         = (const int*)d_in[3];
    const int*   tc         = (const int*)d_in[4];
    const int*   lvl2       = (const int*)d_in[5];
    const int*   lvl1       = (const int*)d_in[6];
    const int*   lvl0       = (const int*)d_in[7];
    const float* comp_table = (const float*)d_in[8];
    const float* op_table   = (const float*)d_in[9];
    const float* W1b        = (const float*)d_in[10];
    const float* b1b        = (const float*)d_in[11];
    const float* W2b        = (const float*)d_in[12];
    const float* b2b        = (const float*)d_in[13];
    const float* W1t        = (const float*)d_in[14];
    const float* b1t        = (const float*)d_in[15];
    const float* W2t        = (const float*)d_in[16];
    const float* b2t        = (const float*)d_in[17];
    const float* gamma      = (const float*)d_in[18];
    const float* beta       = (const float*)d_in[19];
    float* out = (float*)d_out;

    const int n_nodes = in_sizes[0];                 // 65536
    const int L2 = in_sizes[5];                      // 16384
    const int L1 = in_sizes[6];                      // 8192
    const int L0 = in_sizes[7];                      // 4096

    const int SMEM_BIN  = (NPB * 768  + NPB * HID + NPB * D) * 4;  // 98304
    const int SMEM_TERN = (NPB * 1024 + NPB * HID + NPB * D) * 4;  // 114688

    cudaFuncSetAttribute(level_kernel<false>,
                         cudaFuncAttributeMaxDynamicSharedMemorySize, SMEM_BIN);
    cudaFuncSetAttribute(level_kernel<true>,
                         cudaFuncAttributeMaxDynamicSharedMemorySize, SMEM_TERN);

    // 1) embeddings for all nodes
    {
        int total = n_nodes * (D / 4);
        embed_kernel<<<(total + 255) / 256, 256>>>(comp_ids, comp_table, n_nodes);
    }

    // 2) lvl2, ternary slot (phase 0): first 4096 logical nodes -> 256 blocks
    level_kernel<true><<<L0 / NPB, THREADS, SMEM_TERN>>>(
        lvl2, /*phases=*/4, /*blk_off=*/0,
        op_ids, lc, rc, tc, op_table,
        W1t, b1t, W2t, b2t, gamma, beta, nullptr);

    // 3) lvl2, binary slots (phases 1..3): 12288 nodes -> 768 blocks, offset 256
    level_kernel<false><<<(L2 - L0) / NPB, THREADS, SMEM_BIN>>>(
        lvl2, /*phases=*/4, /*blk_off=*/L0 / NPB,
        op_ids, lc, rc, tc, op_table,
        W1b, b1b, W2b, b2b, gamma, beta, nullptr);

    // 4) lvl1 (all binary): 8192 nodes -> 512 blocks
    level_kernel<false><<<L1 / NPB, THREADS, SMEM_BIN>>>(
        lvl1, /*phases=*/2, /*blk_off=*/0,
        op_ids, lc, rc, tc, op_table,
        W1b, b1b, W2b, b2b, gamma, beta, nullptr);

    // 5) lvl0 (all binary): 4096 nodes -> 256 blocks, writes d_out densely
    level_kernel<false><<<L0 / NPB, THREADS, SMEM_BIN>>>(
        lvl0, /*phases=*/1, /*blk_off=*/0,
        op_ids, lc, rc, tc, op_table,
        W1b, b1b, W2b, b2b, gamma, beta, out);

    (void)n_in; (void)out_size;
}

// round 9
// speedup vs baseline: 4.1781x; 2.5807x over previous
#include <cuda_runtime.h>
#include <cuda_bf16.h>
#include <cstdint>
#include <math.h>

#define D 256
#define THREADS 256
#define LDS 72   // smem row stride in bf16 (64 data + 8 pad)

// ===========================================================================
// Static device scratch
// ===========================================================================
__device__ float g_nodes[65536 * D];
__device__ __nv_bfloat16 g_Xt_img[4096  * 3072];
__device__ __nv_bfloat16 g_Xb_img[12288 * 2304];
__device__ __nv_bfloat16 g_H_img [12288 * 1536];
__device__ float g_R[12288 * D];
__device__ int   g_nodes_l[12288];
__device__ __nv_bfloat16 g_W1b_img[512 * 2304];
__device__ __nv_bfloat16 g_W1t_img[512 * 3072];
__device__ __nv_bfloat16 g_W2b_img[256 * 1536];
__device__ __nv_bfloat16 g_W2t_img[256 * 1536];

// ===========================================================================
// Helpers (all sm_80-era PTX: safe for plain sm_103 target)
// ===========================================================================
__device__ __forceinline__ uint32_t smem_u32(const void* p) {
    uint32_t a;
    asm("{ .reg .u64 t; cvta.to.shared.u64 t, %1; cvt.u32.u64 %0, t; }" : "=r"(a) : "l"(p));
    return a;
}
__device__ __forceinline__ void cp_async16(uint32_t saddr, const void* gaddr) {
    asm volatile("cp.async.cg.shared.global [%0], [%1], 16;" :: "r"(saddr), "l"(gaddr));
}
__device__ __forceinline__ void cp_commit() {
    asm volatile("cp.async.commit_group;");
}
__device__ __forceinline__ void ldsm_x4(uint32_t* r, uint32_t addr) {
    asm volatile("ldmatrix.sync.aligned.m8n8.x4.shared.b16 {%0,%1,%2,%3}, [%4];"
                 : "=r"(r[0]), "=r"(r[1]), "=r"(r[2]), "=r"(r[3]) : "r"(addr));
}
__device__ __forceinline__ void mma_bf16(float* c, const uint32_t* a, uint32_t b0, uint32_t b1) {
    asm volatile("mma.sync.aligned.m16n8k16.row.col.f32.bf16.bf16.f32 "
                 "{%0,%1,%2,%3}, {%4,%5,%6,%7}, {%8,%9}, {%0,%1,%2,%3};"
                 : "+f"(c[0]), "+f"(c[1]), "+f"(c[2]), "+f"(c[3])
                 : "r"(a[0]), "r"(a[1]), "r"(a[2]), "r"(a[3]), "r"(b0), "r"(b1));
}
__device__ __forceinline__ float gelu_exact(float a) {
    return 0.5f * a * (1.0f + erff(a * 0.70710678118654752f));
}

// ===========================================================================
__global__ void embed_kernel(const int* __restrict__ comp_ids,
                             const float* __restrict__ comp_table, int n_nodes) {
    int idx = blockIdx.x * blockDim.x + threadIdx.x;
    int total = n_nodes * (D / 4);
    if (idx >= total) return;
    int n = idx >> 6, c = idx & 63;
    const float4* src = (const float4*)(comp_table + (size_t)comp_ids[n] * D);
    ((float4*)(g_nodes + (size_t)n * D))[c] = src[c];
}

// W [K,N] fp32 -> img [N, 3K] bf16 (hi | hi | lo)
__global__ void wprep_kernel(const float* __restrict__ W, __nv_bfloat16* __restrict__ img,
                             int K, int N) {
    int idx = blockIdx.x * 256 + threadIdx.x;
    if (idx >= K * N) return;
    int k = idx / N, n = idx % N;
    float v = W[idx];
    __nv_bfloat16 hi = __float2bfloat16(v);
    __nv_bfloat16 lo = __float2bfloat16(v - __bfloat162float(hi));
    size_t base = (size_t)n * 3 * K;
    img[base + k] = hi;
    img[base + K + k] = hi;
    img[base + 2 * K + k] = lo;
}

// Gather + split: A row = [x_hi | x_lo | x_hi]; residual precompute
template <bool TERN>
__global__ void prep_kernel(const int* __restrict__ lvl_idx, int phases, int goff,
                            const int* __restrict__ op_ids,
                            const int* __restrict__ lc, const int* __restrict__ rc,
                            const int* __restrict__ tc,
                            const float* __restrict__ op_table,
                            __nv_bfloat16* __restrict__ Ximg) {
    constexpr int IN = TERN ? 1024 : 768;
    constexpr int KE = 3 * IN;
    int g = blockIdx.x;
    __shared__ int sids[4];
    int d = threadIdx.x;
    if (d == 0) {
        int gg = goff + g;
        int pos = (gg & 4095) * phases + (gg >> 12);
        int node = lvl_idx[pos];
        sids[0] = op_ids[node];
        sids[1] = lc[node];
        sids[2] = rc[node];
        sids[3] = TERN ? tc[node] : 0;
        g_nodes_l[g] = node;
    }
    __syncthreads();
    float opv = op_table[sids[0] * D + d];
    float lev = g_nodes[(size_t)sids[1] * D + d];
    float rev = g_nodes[(size_t)sids[2] * D + d];
    float tev = TERN ? g_nodes[(size_t)sids[3] * D + d] : 0.0f;
    float xs[4] = {opv, lev, rev, tev};
    __nv_bfloat16* row = Ximg + (size_t)g * KE;
    #pragma unroll
    for (int s = 0; s < (TERN ? 4 : 3); s++) {
        float x = xs[s];
        __nv_bfloat16 hi = __float2bfloat16(x);
        __nv_bfloat16 lo = __float2bfloat16(x - __bfloat162float(hi));
        int i = s * D + d;
        row[i] = hi;
        row[IN + i] = lo;
        row[2 * IN + i] = hi;
    }
    g_R[(size_t)g * D + d] = TERN ? (lev + rev + tev) * (1.0f / 3.0f) : (lev + rev);
}

// ===========================================================================
// HMMA GEMM.  MODE 0: 128x128 tile, bias+gelu -> H image (hi|lo|hi).
//             MODE 1: 64x256 tile, bias+residual+LN -> scatter g_nodes.
//             MODE 2: like 1 but dense out[row].
// A image [M, Keff] row-major bf16; B image [N, Keff] row-major bf16.
// ===========================================================================
template <int MODE>
__global__ void __launch_bounds__(THREADS, 2)
mma_kernel(const __nv_bfloat16* __restrict__ Aimg, const __nv_bfloat16* __restrict__ Bimg,
           int Keff, const float* __restrict__ bvec,
           __nv_bfloat16* __restrict__ Himg, const float* __restrict__ Rres,
           const float* __restrict__ gamma, const float* __restrict__ beta,
           float* __restrict__ outp) {
    constexpr int TM = (MODE == 0) ? 128 : 64;
    constexpr int TN = (MODE == 0) ? 128 : 256;
    constexpr int CHUNK = (TM + TN) * LDS;          // bf16 elems per buffer
    constexpr int WM = TM / 32;                     // warps along M

    extern __shared__ char smem[];
    __nv_bfloat16* sbuf = (__nv_bfloat16*)smem;
    const uint32_t sbase = smem_u32(smem);

    const int tid = threadIdx.x, wid = tid >> 5, lane = tid & 31;
    const int warp_m = wid & (WM - 1);
    const int warp_n = wid / WM;
    const int wm0 = warp_m * 32, wn0 = warp_n * 64;
    const int row0 = blockIdx.x * TM;
    const int cb0 = (MODE == 0) ? blockIdx.y * 128 : 0;

    const __nv_bfloat16* Bblk = Bimg + (size_t)cb0 * Keff;

    float acc[2][8][4];
    #pragma unroll
    for (int mt = 0; mt < 2; mt++)
        #pragma unroll
        for (int nt = 0; nt < 8; nt++)
            #pragma unroll
            for (int q = 0; q < 4; q++) acc[mt][nt][q] = 0.0f;

    // ---- chunk loader (cp.async, 16B granules) ---------------------------
    auto load_chunk = [&](int c, int b) {
        const int base = b * CHUNK;
        const __nv_bfloat16* Ab = Aimg + (size_t)row0 * Keff + c * 64;
        #pragma unroll
        for (int v = tid; v < TM * 8; v += THREADS) {
            int r = v >> 3, s = v & 7;
            cp_async16(sbase + (base + r * LDS + s * 8) * 2,
                       Ab + (size_t)r * Keff + s * 8);
        }
        const __nv_bfloat16* Bb = Bblk + c * 64;
        #pragma unroll
        for (int v = tid; v < TN * 8; v += THREADS) {
            int r = v >> 3, s = v & 7;
            cp_async16(sbase + (base + TM * LDS + r * LDS + s * 8) * 2,
                       Bb + (size_t)r * Keff + s * 8);
        }
        cp_commit();
    };

    const int NC = Keff >> 6;
    load_chunk(0, 0);
    for (int c = 0; c < NC; c++) {
        const int b = c & 1;
        if (c + 1 < NC) {
            load_chunk(c + 1, (c + 1) & 1);
            asm volatile("cp.async.wait_group 1;");
        } else {
            asm volatile("cp.async.wait_group 0;");
        }
        __syncthreads();

        const uint32_t aBase = sbase + (b * CHUNK) * 2;
        const uint32_t bBase = sbase + (b * CHUNK + TM * LDS) * 2;
        #pragma unroll
        for (int ks = 0; ks < 4; ks++) {
            uint32_t afr[2][4];
            #pragma unroll
            for (int mt = 0; mt < 2; mt++) {
                uint32_t ad = aBase +
                    ((wm0 + mt * 16 + (lane & 15)) * LDS + ks * 16 + (lane >> 4) * 8) * 2;
                ldsm_x4(afr[mt], ad);
            }
            uint32_t bfr[4][4];
            #pragma unroll
            for (int ntp = 0; ntp < 4; ntp++) {
                int n = wn0 + ntp * 16 + (lane & 7) + ((lane >> 4) << 3);
                int koff = ks * 16 + ((lane >> 3) & 1) * 8;
                ldsm_x4(bfr[ntp], bBase + (n * LDS + koff) * 2);
            }
            #pragma unroll
            for (int mt = 0; mt < 2; mt++)
                #pragma unroll
                for (int ntp = 0; ntp < 4; ntp++) {
                    mma_bf16(acc[mt][ntp * 2 + 0], afr[mt], bfr[ntp][0], bfr[ntp][1]);
                    mma_bf16(acc[mt][ntp * 2 + 1], afr[mt], bfr[ntp][2], bfr[ntp][3]);
                }
        }
        __syncthreads();
    }

    // ---- epilogue --------------------------------------------------------
    if (MODE == 0) {
        uint32_t* H32 = (uint32_t*)Himg;
        #pragma unroll
        for (int mt = 0; mt < 2; mt++) {
            #pragma unroll
            for (int nt = 0; nt < 8; nt++) {
                int rl = wm0 + mt * 16 + (lane >> 2);
                int j  = cb0 + wn0 + (nt >> 1) * 16 + (nt & 1) * 8 + (lane & 3) * 2;
                float bj0 = __ldg(&bvec[j]);
                float bj1 = __ldg(&bvec[j + 1]);
                #pragma unroll
                for (int hrow = 0; hrow < 2; hrow++) {
                    int row = row0 + rl + hrow * 8;
                    float h0 = gelu_exact(acc[mt][nt][hrow * 2 + 0] + bj0);
                    float h1 = gelu_exact(acc[mt][nt][hrow * 2 + 1] + bj1);
                    __nv_bfloat16 h0h = __float2bfloat16(h0);
                    __nv_bfloat16 h1h = __float2bfloat16(h1);
                    __nv_bfloat16 h0l = __float2bfloat16(h0 - __bfloat162float(h0h));
                    __nv_bfloat16 h1l = __float2bfloat16(h1 - __bfloat162float(h1h));
                    uint32_t hw = (uint32_t)__bfloat16_as_ushort(h1h) << 16 | __bfloat16_as_ushort(h0h);
                    uint32_t lw = (uint32_t)__bfloat16_as_ushort(h1l) << 16 | __bfloat16_as_ushort(h0l);
                    size_t rb = (size_t)row * 768;     // 1536 bf16 / 2
                    H32[rb + (j >> 1)]       = hw;     // seg0: hi
                    H32[rb + 256 + (j >> 1)] = lw;     // seg1: lo
                    H32[rb + 512 + (j >> 1)] = hw;     // seg2: hi
                }
            }
        }
    } else {
        float* sy = (float*)smem;                      // [64][257]
        #pragma unroll
        for (int mt = 0; mt < 2; mt++) {
            #pragma unroll
            for (int nt = 0; nt < 8; nt++) {
                int rl  = wm0 + mt * 16 + (lane >> 2);
                int col = wn0 + (nt >> 1) * 16 + (nt & 1) * 8 + (lane & 3) * 2;
                float b0 = __ldg(&bvec[col]);
                float b1 = __ldg(&bvec[col + 1]);
                #pragma unroll
                for (int hrow = 0; hrow < 2; hrow++) {
                    int r = rl + hrow * 8;
                    int pos = row0 + r;
                    float r0 = __ldg(&Rres[(size_t)pos * D + col]);
                    float r1 = __ldg(&Rres[(size_t)pos * D + col + 1]);
                    sy[r * 257 + col]     = acc[mt][nt][hrow * 2 + 0] + b0 + r0;
                    sy[r * 257 + col + 1] = acc[mt][nt][hrow * 2 + 1] + b1 + r1;
                }
            }
        }
        __syncthreads();
        #pragma unroll
        for (int rr = 0; rr < 8; rr++) {
            int rn = wid * 8 + rr;
            int pos = row0 + rn;
            float vals[8];
            float s = 0.0f, s2 = 0.0f;
            #pragma unroll
            for (int k = 0; k < 8; k++) {
                float v = sy[rn * 257 + lane + k * 32];
                vals[k] = v; s += v; s2 = fmaf(v, v, s2);
            }
            #pragma unroll
            for (int off = 16; off > 0; off >>= 1) {
                s  += __shfl_xor_sync(0xFFFFFFFF, s, off);
                s2 += __shfl_xor_sync(0xFFFFFFFF, s2, off);
            }
            float mu  = s * (1.0f / 256.0f);
            float var = s2 * (1.0f / 256.0f) - mu * mu;
            float inv = rsqrtf(var + 1e-5f);
            float* dst = (MODE == 1) ? outp + (size_t)g_nodes_l[pos] * D
                                     : outp + (size_t)pos * D;
            #pragma unroll
            for (int k = 0; k < 8; k++) {
                int d = lane + k * 32;
                dst[d] = (vals[k] - mu) * inv * __ldg(&gamma[d]) + __ldg(&beta[d]);
            }
        }
    }
}

// ===========================================================================
extern "C" void kernel_launch(void* const* d_in, const int* in_sizes, int n_in,
                              void* d_out, int out_size) {
    const int*   comp_ids   = (const int*)d_in[0];
    const int*   op_ids     = (const int*)d_in[1];
    const int*   lc         = (const int*)d_in[2];
    const int*   rc         = (const int*)d_in[3];
    const int*   tc         = (const int*)d_in[4];
    const int*   lvl2       = (const int*)d_in[5];
    const int*   lvl1       = (const int*)d_in[6];
    const int*   lvl0       = (const int*)d_in[7];
    const float* comp_table = (const float*)d_in[8];
    const float* op_table   = (const float*)d_in[9];
    const float* W1b        = (const float*)d_in[10];
    const float* b1b        = (const float*)d_in[11];
    const float* W2b        = (const float*)d_in[12];
    const float* b2b        = (const float*)d_in[13];
    const float* W1t        = (const float*)d_in[14];
    const float* b1t        = (const float*)d_in[15];
    const float* W2t        = (const float*)d_in[16];
    const float* b2t        = (const float*)d_in[17];
    const float* gamma      = (const float*)d_in[18];
    const float* beta       = (const float*)d_in[19];
    float* out = (float*)d_out;

    const int n_nodes = in_sizes[0];

    float* p_gnodes;  cudaGetSymbolAddress((void**)&p_gnodes, g_nodes);
    float* p_R;       cudaGetSymbolAddress((void**)&p_R, g_R);
    __nv_bfloat16 *p_Xt, *p_Xb, *p_H, *p_W1b, *p_W1t, *p_W2b, *p_W2t;
    cudaGetSymbolAddress((void**)&p_Xt,  g_Xt_img);
    cudaGetSymbolAddress((void**)&p_Xb,  g_Xb_img);
    cudaGetSymbolAddress((void**)&p_H,   g_H_img);
    cudaGetSymbolAddress((void**)&p_W1b, g_W1b_img);
    cudaGetSymbolAddress((void**)&p_W1t, g_W1t_img);
    cudaGetSymbolAddress((void**)&p_W2b, g_W2b_img);
    cudaGetSymbolAddress((void**)&p_W2t, g_W2t_img);

    const int SMEM0 = 2 * (128 + 128) * LDS * 2;   // 73,728
    const int SMEM1 = 2 * (64 + 256) * LDS * 2;    // 92,160
    cudaFuncSetAttribute(mma_kernel<0>, cudaFuncAttributeMaxDynamicSharedMemorySize, SMEM0);
    cudaFuncSetAttribute(mma_kernel<1>, cudaFuncAttributeMaxDynamicSharedMemorySize, SMEM1);
    cudaFuncSetAttribute(mma_kernel<2>, cudaFuncAttributeMaxDynamicSharedMemorySize, SMEM1);

    embed_kernel<<<(n_nodes * (D / 4) + 255) / 256, 256>>>(comp_ids, comp_table, n_nodes);
    wprep_kernel<<<(768 * 512 + 255) / 256, 256>>>(W1b, p_W1b, 768, 512);
    wprep_kernel<<<(1024 * 512 + 255) / 256, 256>>>(W1t, p_W1t, 1024, 512);
    wprep_kernel<<<(512 * 256 + 255) / 256, 256>>>(W2b, p_W2b, 512, 256);
    wprep_kernel<<<(512 * 256 + 255) / 256, 256>>>(W2t, p_W2t, 512, 256);

    // lvl2 ternary (slot 3): rows 0..4095
    prep_kernel<true><<<4096, 256>>>(lvl2, 4, 0, op_ids, lc, rc, tc, op_table, p_Xt);
    mma_kernel<0><<<dim3(32, 4), THREADS, SMEM0>>>(
        p_Xt, p_W1t, 3072, b1t, p_H, nullptr, gamma, beta, nullptr);
    mma_kernel<1><<<64, THREADS, SMEM1>>>(
        p_H, p_W2t, 1536, b2t, nullptr, p_R, gamma, beta, p_gnodes);

    // lvl2 binary (slots 4,5,6): rows 0..12287
    prep_kernel<false><<<12288, 256>>>(lvl2, 4, 4096, op_ids, lc, rc, tc, op_table, p_Xb);
    mma_kernel<0><<<dim3(96, 4), THREADS, SMEM0>>>(
        p_Xb, p_W1b, 2304, b1b, p_H, nullptr, gamma, beta, nullptr);
    mma_kernel<1><<<192, THREADS, SMEM1>>>(
        p_H, p_W2b, 1536, b2b, nullptr, p_R, gamma, beta, p_gnodes);

    // lvl1 (slots 1,2): 8192 nodes
    prep_kernel<false><<<8192, 256>>>(lvl1, 2, 0, op_ids, lc, rc, tc, op_table, p_Xb);
    mma_kernel<0><<<dim3(64, 4), THREADS, SMEM0>>>(
        p_Xb, p_W1b, 2304, b1b, p_H, nullptr, gamma, beta, nullptr);
    mma_kernel<1><<<128, THREADS, SMEM1>>>(
        p_H, p_W2b, 1536, b2b, nullptr, p_R, gamma, beta, p_gnodes);

    // lvl0 (slot 0): 4096 nodes -> dense out
    prep_kernel<false><<<4096, 256>>>(lvl0, 1, 0, op_ids, lc, rc, tc, op_table, p_Xb);
    mma_kernel<0><<<dim3(32, 4), THREADS, SMEM0>>>(
        p_Xb, p_W1b, 2304, b1b, p_H, nullptr, gamma, beta, nullptr);
    mma_kernel<2><<<64, THREADS, SMEM1>>>(
        p_H, p_W2b, 1536, b2b, nullptr, p_R, gamma, beta, out);

    (void)n_in; (void)out_size;
}

// round 10
// speedup vs baseline: 4.8732x; 1.1664x over previous
#include <cuda_runtime.h>
#include <cuda_bf16.h>
#include <cstdint>
#include <math.h>

#define D 256
#define THREADS 256
#define LDS 72   // smem row stride in bf16 (64 data + 8 pad)

// ===========================================================================
// Static device scratch
// ===========================================================================
__device__ float g_nodes[65536 * D];                    // internal-node embeddings
__device__ __nv_bfloat16 g_Xt_img[4096  * 1536];        // ternary X  [hi768|lo768]
__device__ __nv_bfloat16 g_Xb_img[12288 * 1024];        // binary  X  [hi512|lo512]
__device__ __nv_bfloat16 g_H_img [12288 * 1024];        // H          [hi512|lo512]
__device__ float g_R[12288 * D];
__device__ int   g_nodes_l[12288];
__device__ int   g_op_l[12288];
__device__ __nv_bfloat16 g_W1b_img[512 * 1024];         // [N=512][whi512|wlo512]
__device__ __nv_bfloat16 g_W1t_img[512 * 1536];         // [N=512][whi768|wlo768]
__device__ __nv_bfloat16 g_W2b_img[256 * 1024];
__device__ __nv_bfloat16 g_W2t_img[256 * 1024];
__device__ float g_opb_b[16 * 512];                     // b1 + op_e @ W1[0:256]
__device__ float g_opb_t[16 * 512];

// ===========================================================================
// Helpers (sm_80-era PTX only — safe for plain sm_103 ptxas target)
// ===========================================================================
__device__ __forceinline__ uint32_t smem_u32(const void* p) {
    uint32_t a;
    asm("{ .reg .u64 t; cvta.to.shared.u64 t, %1; cvt.u32.u64 %0, t; }" : "=r"(a) : "l"(p));
    return a;
}
__device__ __forceinline__ void cp_async16(uint32_t saddr, const void* gaddr) {
    asm volatile("cp.async.cg.shared.global [%0], [%1], 16;" :: "r"(saddr), "l"(gaddr));
}
__device__ __forceinline__ void cp_commit() {
    asm volatile("cp.async.commit_group;");
}
__device__ __forceinline__ void ldsm_x4(uint32_t* r, uint32_t addr) {
    asm volatile("ldmatrix.sync.aligned.m8n8.x4.shared.b16 {%0,%1,%2,%3}, [%4];"
                 : "=r"(r[0]), "=r"(r[1]), "=r"(r[2]), "=r"(r[3]) : "r"(addr));
}
__device__ __forceinline__ void mma_bf16(float* c, const uint32_t* a, uint32_t b0, uint32_t b1) {
    asm volatile("mma.sync.aligned.m16n8k16.row.col.f32.bf16.bf16.f32 "
                 "{%0,%1,%2,%3}, {%4,%5,%6,%7}, {%8,%9}, {%0,%1,%2,%3};"
                 : "+f"(c[0]), "+f"(c[1]), "+f"(c[2]), "+f"(c[3])
                 : "r"(a[0]), "r"(a[1]), "r"(a[2]), "r"(a[3]), "r"(b0), "r"(b1));
}
__device__ __forceinline__ float gelu_exact(float a) {
    return 0.5f * a * (1.0f + erff(a * 0.70710678118654752f));
}

// ===========================================================================
// Weight image: W_sub [K,N] fp32 -> img [N][2K] bf16 ([hi(K)|lo(K)])
// ===========================================================================
__global__ void wprep_kernel(const float* __restrict__ W, __nv_bfloat16* __restrict__ img,
                             int K, int N) {
    int idx = blockIdx.x * 256 + threadIdx.x;
    if (idx >= K * N) return;
    int k = idx / N, n = idx % N;
    float v = W[idx];
    __nv_bfloat16 hi = __float2bfloat16(v);
    __nv_bfloat16 lo = __float2bfloat16(v - __bfloat162float(hi));
    size_t base = (size_t)n * 2 * K;
    img[base + k] = hi;
    img[base + K + k] = lo;
}

// opbias[o][j] = b1[j] + sum_{k<256} op_table[o][k] * W1[k][j]   (exact fp32)
__global__ void opproj_kernel(const float* __restrict__ op_table,
                              const float* __restrict__ W1,
                              const float* __restrict__ b1,
                              float* __restrict__ outb) {
    int idx = blockIdx.x * 256 + threadIdx.x;   // 16*512 threads
    int o = idx >> 9, j = idx & 511;
    float s = b1[j];
    const float* oe = op_table + o * D;
    #pragma unroll 8
    for (int k = 0; k < D; k++)
        s = fmaf(oe[k], W1[(size_t)k * 512 + j], s);
    outb[idx] = s;
}

// ===========================================================================
// X prep: gather children, split hi/lo -> X image [hi(K)|lo(K)]; residual
// LEAF: children come from comp_table[comp_ids[child]] (lvl2); else g_nodes.
// ===========================================================================
template <bool TERN, bool LEAF>
__global__ void prep_kernel(const int* __restrict__ lvl_idx, int phases, int goff,
                            const int* __restrict__ op_ids,
                            const int* __restrict__ lc, const int* __restrict__ rc,
                            const int* __restrict__ tc,
                            const int* __restrict__ comp_ids,
                            const float* __restrict__ comp_table,
                            __nv_bfloat16* __restrict__ Ximg) {
    constexpr int K = TERN ? 768 : 512;
    int g = blockIdx.x;
    __shared__ int sids[3];
    int d = threadIdx.x;
    if (d == 0) {
        int gg = goff + g;
        int pos = (gg & 4095) * phases + (gg >> 12);
        int node = lvl_idx[pos];
        int l = lc[node], r = rc[node];
        sids[0] = LEAF ? comp_ids[l] : l;
        sids[1] = LEAF ? comp_ids[r] : r;
        if (TERN) { int t = tc[node]; sids[2] = LEAF ? comp_ids[t] : t; }
        g_nodes_l[g] = node;
        g_op_l[g] = op_ids[node];
    }
    __syncthreads();
    const float* src = LEAF ? comp_table : g_nodes;
    float lev = src[(size_t)sids[0] * D + d];
    float rev = src[(size_t)sids[1] * D + d];
    float tev = TERN ? src[(size_t)sids[2] * D + d] : 0.0f;
    float xs[3] = {lev, rev, tev};
    __nv_bfloat16* row = Ximg + (size_t)g * 2 * K;
    #pragma unroll
    for (int s = 0; s < (TERN ? 3 : 2); s++) {
        float x = xs[s];
        __nv_bfloat16 hi = __float2bfloat16(x);
        __nv_bfloat16 lo = __float2bfloat16(x - __bfloat162float(hi));
        int i = s * D + d;
        row[i] = hi;
        row[K + i] = lo;
    }
    g_R[(size_t)g * D + d] = TERN ? (lev + rev + tev) * (1.0f / 3.0f) : (lev + rev);
}

// ===========================================================================
// HMMA GEMM with 3-term logical K ([hi|lo|hi] x [whi|whi|wlo]) over 2-term
// physical images. Chunk remap: srcA = c<2*KC ? c : c-2*KC ; srcB = c<KC ? c : c-KC.
// MODE 0: 128x128 tile, per-row opbias + gelu -> H image [hi|lo].
// MODE 1: 64x256 tile, bias+residual+LN -> scatter g_nodes.
// MODE 2: like 1 but dense out[row].
// ===========================================================================
template <int MODE>
__global__ void __launch_bounds__(THREADS, 2)
mma_kernel(const __nv_bfloat16* __restrict__ Aimg, const __nv_bfloat16* __restrict__ Bimg,
           int KC, const float* __restrict__ bvec,
           __nv_bfloat16* __restrict__ Himg, const float* __restrict__ Rres,
           const float* __restrict__ gamma, const float* __restrict__ beta,
           float* __restrict__ outp) {
    constexpr int TM = (MODE == 0) ? 128 : 64;
    constexpr int TN = (MODE == 0) ? 128 : 256;
    constexpr int CHUNK = (TM + TN) * LDS;          // bf16 elems per buffer
    constexpr int WM = TM / 32;                     // warps along M

    extern __shared__ char smem[];
    const uint32_t sbase = smem_u32(smem);

    const int tid = threadIdx.x, wid = tid >> 5, lane = tid & 31;
    const int warp_m = wid & (WM - 1);
    const int warp_n = wid / WM;
    const int wm0 = warp_m * 32, wn0 = warp_n * 64;
    const int row0 = blockIdx.x * TM;
    const int cb0 = (MODE == 0) ? blockIdx.y * 128 : 0;

    const int stride = 2 * KC * 64;                 // physical row width (bf16)
    const __nv_bfloat16* Bblk = Bimg + (size_t)cb0 * stride;

    float acc[2][8][4];
    #pragma unroll
    for (int mt = 0; mt < 2; mt++)
        #pragma unroll
        for (int nt = 0; nt < 8; nt++)
            #pragma unroll
            for (int q = 0; q < 4; q++) acc[mt][nt][q] = 0.0f;

    auto load_chunk = [&](int cA, int cB, int b) {
        const int base = b * CHUNK;
        const __nv_bfloat16* Ab = Aimg + (size_t)row0 * stride + cA * 64;
        #pragma unroll
        for (int v = tid; v < TM * 8; v += THREADS) {
            int r = v >> 3, s = v & 7;
            cp_async16(sbase + (base + r * LDS + s * 8) * 2,
                       Ab + (size_t)r * stride + s * 8);
        }
        const __nv_bfloat16* Bb = Bblk + cB * 64;
        #pragma unroll
        for (int v = tid; v < TN * 8; v += THREADS) {
            int r = v >> 3, s = v & 7;
            cp_async16(sbase + (base + TM * LDS + r * LDS + s * 8) * 2,
                       Bb + (size_t)r * stride + s * 8);
        }
        cp_commit();
    };

    const int NC = 3 * KC;
    auto srcA = [&](int c) { return (c < 2 * KC) ? c : c - 2 * KC; };
    auto srcB = [&](int c) { return (c < KC) ? c : c - KC; };

    load_chunk(0, 0, 0);
    for (int c = 0; c < NC; c++) {
        const int b = c & 1;
        if (c + 1 < NC) {
            load_chunk(srcA(c + 1), srcB(c + 1), (c + 1) & 1);
            asm volatile("cp.async.wait_group 1;");
        } else {
            asm volatile("cp.async.wait_group 0;");
        }
        __syncthreads();

        const uint32_t aBase = sbase + (b * CHUNK) * 2;
        const uint32_t bBase = sbase + (b * CHUNK + TM * LDS) * 2;
        #pragma unroll
        for (int ks = 0; ks < 4; ks++) {
            uint32_t afr[2][4];
            #pragma unroll
            for (int mt = 0; mt < 2; mt++) {
                uint32_t ad = aBase +
                    ((wm0 + mt * 16 + (lane & 15)) * LDS + ks * 16 + (lane >> 4) * 8) * 2;
                ldsm_x4(afr[mt], ad);
            }
            uint32_t bfr[4][4];
            #pragma unroll
            for (int ntp = 0; ntp < 4; ntp++) {
                int n = wn0 + ntp * 16 + (lane & 7) + ((lane >> 4) << 3);
                int koff = ks * 16 + ((lane >> 3) & 1) * 8;
                ldsm_x4(bfr[ntp], bBase + (n * LDS + koff) * 2);
            }
            #pragma unroll
            for (int mt = 0; mt < 2; mt++)
                #pragma unroll
                for (int ntp = 0; ntp < 4; ntp++) {
                    mma_bf16(acc[mt][ntp * 2 + 0], afr[mt], bfr[ntp][0], bfr[ntp][1]);
                    mma_bf16(acc[mt][ntp * 2 + 1], afr[mt], bfr[ntp][2], bfr[ntp][3]);
                }
        }
        __syncthreads();
    }

    // ---- epilogue --------------------------------------------------------
    if (MODE == 0) {
        uint32_t* H32 = (uint32_t*)Himg;
        #pragma unroll
        for (int mt = 0; mt < 2; mt++) {
            #pragma unroll
            for (int nt = 0; nt < 8; nt++) {
                int rl = wm0 + mt * 16 + (lane >> 2);
                int j  = cb0 + wn0 + (nt >> 1) * 16 + (nt & 1) * 8 + (lane & 3) * 2;
                #pragma unroll
                for (int hrow = 0; hrow < 2; hrow++) {
                    int row = row0 + rl + hrow * 8;
                    int op = g_op_l[row];
                    float bj0 = __ldg(&bvec[op * 512 + j]);
                    float bj1 = __ldg(&bvec[op * 512 + j + 1]);
                    float h0 = gelu_exact(acc[mt][nt][hrow * 2 + 0] + bj0);
                    float h1 = gelu_exact(acc[mt][nt][hrow * 2 + 1] + bj1);
                    __nv_bfloat16 h0h = __float2bfloat16(h0);
                    __nv_bfloat16 h1h = __float2bfloat16(h1);
                    __nv_bfloat16 h0l = __float2bfloat16(h0 - __bfloat162float(h0h));
                    __nv_bfloat16 h1l = __float2bfloat16(h1 - __bfloat162float(h1h));
                    uint32_t hw = (uint32_t)__bfloat16_as_ushort(h1h) << 16 | __bfloat16_as_ushort(h0h);
                    uint32_t lw = (uint32_t)__bfloat16_as_ushort(h1l) << 16 | __bfloat16_as_ushort(h0l);
                    size_t rb = (size_t)row * 512;       // 1024 bf16 / 2
                    H32[rb + (j >> 1)]       = hw;       // hi segment
                    H32[rb + 256 + (j >> 1)] = lw;       // lo segment
                }
            }
        }
    } else {
        float* sy = (float*)smem;                        // [64][257]
        #pragma unroll
        for (int mt = 0; mt < 2; mt++) {
            #pragma unroll
            for (int nt = 0; nt < 8; nt++) {
                int rl  = wm0 + mt * 16 + (lane >> 2);
                int col = wn0 + (nt >> 1) * 16 + (nt & 1) * 8 + (lane & 3) * 2;
                float b0 = __ldg(&bvec[col]);
                float b1 = __ldg(&bvec[col + 1]);
                #pragma unroll
                for (int hrow = 0; hrow < 2; hrow++) {
                    int r = rl + hrow * 8;
                    int pos = row0 + r;
                    float r0 = __ldg(&Rres[(size_t)pos * D + col]);
                    float r1 = __ldg(&Rres[(size_t)pos * D + col + 1]);
                    sy[r * 257 + col]     = acc[mt][nt][hrow * 2 + 0] + b0 + r0;
                    sy[r * 257 + col + 1] = acc[mt][nt][hrow * 2 + 1] + b1 + r1;
                }
            }
        }
        __syncthreads();
        #pragma unroll
        for (int rr = 0; rr < 8; rr++) {
            int rn = wid * 8 + rr;
            int pos = row0 + rn;
            float vals[8];
            float s = 0.0f, s2 = 0.0f;
            #pragma unroll
            for (int k = 0; k < 8; k++) {
                float v = sy[rn * 257 + lane + k * 32];
                vals[k] = v; s += v; s2 = fmaf(v, v, s2);
            }
            #pragma unroll
            for (int off = 16; off > 0; off >>= 1) {
                s  += __shfl_xor_sync(0xFFFFFFFF, s, off);
                s2 += __shfl_xor_sync(0xFFFFFFFF, s2, off);
            }
            float mu  = s * (1.0f / 256.0f);
            float var = s2 * (1.0f / 256.0f) - mu * mu;
            float inv = rsqrtf(var + 1e-5f);
            float* dst = (MODE == 1) ? outp + (size_t)g_nodes_l[pos] * D
                                     : outp + (size_t)pos * D;
            #pragma unroll
            for (int k = 0; k < 8; k++) {
                int d = lane + k * 32;
                dst[d] = (vals[k] - mu) * inv * __ldg(&gamma[d]) + __ldg(&beta[d]);
            }
        }
    }
}

// ===========================================================================
extern "C" void kernel_launch(void* const* d_in, const int* in_sizes, int n_in,
                              void* d_out, int out_size) {
    const int*   comp_ids   = (const int*)d_in[0];
    const int*   op_ids     = (const int*)d_in[1];
    const int*   lc         = (const int*)d_in[2];
    const int*   rc         = (const int*)d_in[3];
    const int*   tc         = (const int*)d_in[4];
    const int*   lvl2       = (const int*)d_in[5];
    const int*   lvl1       = (const int*)d_in[6];
    const int*   lvl0       = (const int*)d_in[7];
    const float* comp_table = (const float*)d_in[8];
    const float* op_table   = (const float*)d_in[9];
    const float* W1b        = (const float*)d_in[10];
    const float* b1b        = (const float*)d_in[11];
    const float* W2b        = (const float*)d_in[12];
    const float* b2b        = (const float*)d_in[13];
    const float* W1t        = (const float*)d_in[14];
    const float* b1t        = (const float*)d_in[15];
    const float* W2t        = (const float*)d_in[16];
    const float* b2t        = (const float*)d_in[17];
    const float* gamma      = (const float*)d_in[18];
    const float* beta       = (const float*)d_in[19];
    float* out = (float*)d_out;

    float* p_gnodes;  cudaGetSymbolAddress((void**)&p_gnodes, g_nodes);
    float* p_R;       cudaGetSymbolAddress((void**)&p_R, g_R);
    float* p_opb_b;   cudaGetSymbolAddress((void**)&p_opb_b, g_opb_b);
    float* p_opb_t;   cudaGetSymbolAddress((void**)&p_opb_t, g_opb_t);
    __nv_bfloat16 *p_Xt, *p_Xb, *p_H, *p_W1b, *p_W1t, *p_W2b, *p_W2t;
    cudaGetSymbolAddress((void**)&p_Xt,  g_Xt_img);
    cudaGetSymbolAddress((void**)&p_Xb,  g_Xb_img);
    cudaGetSymbolAddress((void**)&p_H,   g_H_img);
    cudaGetSymbolAddress((void**)&p_W1b, g_W1b_img);
    cudaGetSymbolAddress((void**)&p_W1t, g_W1t_img);
    cudaGetSymbolAddress((void**)&p_W2b, g_W2b_img);
    cudaGetSymbolAddress((void**)&p_W2t, g_W2t_img);

    const int SMEM0 = 2 * (128 + 128) * LDS * 2;   // 73,728
    const int SMEM1 = 2 * (64 + 256) * LDS * 2;    // 92,160
    cudaFuncSetAttribute(mma_kernel<0>, cudaFuncAttributeMaxDynamicSharedMemorySize, SMEM0);
    cudaFuncSetAttribute(mma_kernel<1>, cudaFuncAttributeMaxDynamicSharedMemorySize, SMEM1);
    cudaFuncSetAttribute(mma_kernel<2>, cudaFuncAttributeMaxDynamicSharedMemorySize, SMEM1);

    // Weight images (op rows excluded from W1: start at row 256)
    wprep_kernel<<<(512 * 512 + 255) / 256, 256>>>(W1b + 256 * 512, p_W1b, 512, 512);
    wprep_kernel<<<(768 * 512 + 255) / 256, 256>>>(W1t + 256 * 512, p_W1t, 768, 512);
    wprep_kernel<<<(512 * 256 + 255) / 256, 256>>>(W2b, p_W2b, 512, 256);
    wprep_kernel<<<(512 * 256 + 255) / 256, 256>>>(W2t, p_W2t, 512, 256);
    // Exact op-contribution tables (b1 folded in)
    opproj_kernel<<<32, 256>>>(op_table, W1b, b1b, p_opb_b);
    opproj_kernel<<<32, 256>>>(op_table, W1t, b1t, p_opb_t);

    // lvl2 ternary (slot 3): rows 0..4095, leaf children  — KC=12
    prep_kernel<true, true><<<4096, 256>>>(lvl2, 4, 0, op_ids, lc, rc, tc,
                                           comp_ids, comp_table, p_Xt);
    mma_kernel<0><<<dim3(32, 4), THREADS, SMEM0>>>(
        p_Xt, p_W1t, 12, p_opb_t, p_H, nullptr, gamma, beta, nullptr);
    mma_kernel<1><<<64, THREADS, SMEM1>>>(
        p_H, p_W2t, 8, b2t, nullptr, p_R, gamma, beta, p_gnodes);

    // lvl2 binary (slots 4,5,6): rows 0..12287, leaf children — KC=8
    prep_kernel<false, true><<<12288, 256>>>(lvl2, 4, 4096, op_ids, lc, rc, tc,
                                             comp_ids, comp_table, p_Xb);
    mma_kernel<0><<<dim3(96, 4), THREADS, SMEM0>>>(
        p_Xb, p_W1b, 8, p_opb_b, p_H, nullptr, gamma, beta, nullptr);
    mma_kernel<1><<<192, THREADS, SMEM1>>>(
        p_H, p_W2b, 8, b2b, nullptr, p_R, gamma, beta, p_gnodes);

    // lvl1 (slots 1,2): 8192 nodes, internal children
    prep_kernel<false, false><<<8192, 256>>>(lvl1, 2, 0, op_ids, lc, rc, tc,
                                             comp_ids, comp_table, p_Xb);
    mma_kernel<0><<<dim3(64, 4), THREADS, SMEM0>>>(
        p_Xb, p_W1b, 8, p_opb_b, p_H, nullptr, gamma, beta, nullptr);
    mma_kernel<1><<<128, THREADS, SMEM1>>>(
        p_H, p_W2b, 8, b2b, nullptr, p_R, gamma, beta, p_gnodes);

    // lvl0 (slot 0): 4096 nodes -> dense out
    prep_kernel<false, false><<<4096, 256>>>(lvl0, 1, 0, op_ids, lc, rc, tc,
                                             comp_ids, comp_table, p_Xb);
    mma_kernel<0><<<dim3(32, 4), THREADS, SMEM0>>>(
        p_Xb, p_W1b, 8, p_opb_b, p_H, nullptr, gamma, beta, nullptr);
    mma_kernel<2><<<64, THREADS, SMEM1>>>(
        p_H, p_W2b, 8, b2b, nullptr, p_R, gamma, beta, out);

    (void)n_in; (void)out_size;
}